// round 1
// baseline (speedup 1.0000x reference)
#include <cuda_runtime.h>
#include <math.h>

// Problem constants
#define B_ 2
#define Q_ 75
#define N_ 5
#define T_ 196
#define C_ 384
#define D_ 384

// Tiling
#define DT 32            // d-tile (rows of S / channels of fq_new per slab)
#define NDT (C_ / DT)    // 12
#define TK 8             // t-chunk for GEMM1
#define CK 32            // c-chunk for GEMM2
#define TPB 256
#define SFQ_STRIDE 225   // odd stride, covers t in [0,224]
#define PT_STRIDE 33     // odd stride for transposed P tile

// Shared memory layout (in floats)
#define OFF_S   0
#define OFF_PT  (OFF_S  + DT * C_)          // S slab [32][384]
#define OFF_Q   (OFF_PT + C_ * PT_STRIDE)   // P^T    [384][33]
#define OFF_K   (OFF_Q  + TK * DT)          // Fq slice staging [8][32]
#define OFF_FQ  (OFF_K  + TK * C_)          // Fs chunk staging [8][384]
#define OFF_NUM (OFF_FQ + CK * SFQ_STRIDE)  // Fq c-chunk (transposed) [32][225]
#define OFF_NRM (OFF_NUM + T_)
#define OFF_NFS (OFF_NRM + T_)
#define OFF_RED (OFF_NFS + T_)
#define OFF_PN  (OFF_RED + 8)               // per-warpgroup partial num [8][196]
#define OFF_PQ  (OFF_PN + 8 * T_)           // per-warpgroup partial norm2 [8][196]
#define SMEM_FLOATS (OFF_PQ + 8 * T_)

__device__ float g_top1[B_ * Q_ * N_];

__global__ __launch_bounds__(TPB, 1)
void episodic_main_kernel(const float* __restrict__ fq_g,
                          const float* __restrict__ fs_g) {
    extern __shared__ float sm[];
    float* sS   = sm + OFF_S;
    float* sPT  = sm + OFF_PT;
    float* sQ   = sm + OFF_Q;
    float* sK   = sm + OFF_K;
    float* sFq  = sm + OFF_FQ;
    float* sNum = sm + OFF_NUM;
    float* sNrm = sm + OFF_NRM;
    float* sNfs = sm + OFF_NFS;
    float* sRed = sm + OFF_RED;
    float* sPN  = sm + OFF_PN;
    float* sPQ  = sm + OFF_PQ;

    const int bx = blockIdx.x;
    const int nn = bx % N_;
    const int qq = (bx / N_) % Q_;
    const int bb = bx / (N_ * Q_);

    const float* __restrict__ Fq = fq_g + (size_t)(bb * Q_ + qq) * T_ * C_;
    const float* __restrict__ Fs = fs_g + (size_t)(bb * N_ + nn) * T_ * C_;

    const int tid = threadIdx.x;
    const int wid = tid >> 5;
    const int lid = tid & 31;
    const float scale = 1.0f / 14.0f;  // 1/sqrt(k*t) = 1/sqrt(196)

    // ---- init accumulators + Fs per-token L2 norms ----
    for (int t = tid; t < T_; t += TPB) { sNum[t] = 0.f; sNrm[t] = 0.f; }
    for (int r = wid; r < T_; r += 8) {
        float s = 0.f;
        #pragma unroll
        for (int u = 0; u < C_ / 32; u++) {
            float v = Fs[r * C_ + lid + 32 * u];
            s += v * v;
        }
        #pragma unroll
        for (int o = 16; o > 0; o >>= 1) s += __shfl_xor_sync(0xffffffffu, s, o);
        if (lid == 0) sNfs[r] = sqrtf(s);
    }
    __syncthreads();

    // ===================== d-tile loop =====================
    for (int dt = 0; dt < NDT; dt++) {
        const int d0 = dt * DT;

        // ---- GEMM1: S[i][c] = scale * sum_t Fq[t][d0+i] * Fs[t][c] ----
        {
            const int ty = tid >> 4;   // 0..15 -> 2 d-rows each
            const int tx = tid & 15;   // 0..15 -> 6 interleaved float4 c-chunks
            float acc[2][6][4];
            #pragma unroll
            for (int j = 0; j < 2; j++)
                #pragma unroll
                for (int m = 0; m < 6; m++)
                    #pragma unroll
                    for (int e = 0; e < 4; e++) acc[j][m][e] = 0.f;

            for (int t0 = 0; t0 < T_; t0 += TK) {
                // stage Fs chunk [TK][384] (zero-pad past T_)
                for (int idx = tid; idx < TK * (C_ / 4); idx += TPB) {
                    int row = idx / (C_ / 4);
                    int c4  = idx % (C_ / 4);
                    int t   = t0 + row;
                    float4 v = make_float4(0.f, 0.f, 0.f, 0.f);
                    if (t < T_) v = *(const float4*)&Fs[t * C_ + c4 * 4];
                    ((float4*)sK)[row * (C_ / 4) + c4] = v;
                }
                // stage Fq d-slice [TK][32]
                {
                    int row = tid >> 5;  // TK*DT == 256 exactly
                    int i   = tid & 31;
                    int t   = t0 + row;
                    sQ[row * DT + i] = (t < T_) ? Fq[t * C_ + d0 + i] : 0.f;
                }
                __syncthreads();
                #pragma unroll
                for (int tt = 0; tt < TK; tt++) {
                    float a0 = sQ[tt * DT + ty * 2 + 0];
                    float a1 = sQ[tt * DT + ty * 2 + 1];
                    #pragma unroll
                    for (int m = 0; m < 6; m++) {
                        float4 b = ((const float4*)sK)[tt * (C_ / 4) + tx + 16 * m];
                        acc[0][m][0] += a0 * b.x; acc[0][m][1] += a0 * b.y;
                        acc[0][m][2] += a0 * b.z; acc[0][m][3] += a0 * b.w;
                        acc[1][m][0] += a1 * b.x; acc[1][m][1] += a1 * b.y;
                        acc[1][m][2] += a1 * b.z; acc[1][m][3] += a1 * b.w;
                    }
                }
                __syncthreads();
            }
            // write S slab
            #pragma unroll
            for (int j = 0; j < 2; j++) {
                #pragma unroll
                for (int m = 0; m < 6; m++) {
                    float4 v = make_float4(acc[j][m][0] * scale, acc[j][m][1] * scale,
                                           acc[j][m][2] * scale, acc[j][m][3] * scale);
                    *(float4*)&sS[(ty * 2 + j) * C_ + 4 * (tx + 16 * m)] = v;
                }
            }
            __syncthreads();
        }

        // ---- row softmax of S slab; write transposed into sPT[c][i] ----
        {
            #pragma unroll
            for (int k = 0; k < DT / 8; k++) {
                int r = wid * (DT / 8) + k;
                float v[C_ / 32];
                float mx = -INFINITY;
                #pragma unroll
                for (int u = 0; u < C_ / 32; u++) {
                    v[u] = sS[r * C_ + lid + 32 * u];
                    mx = fmaxf(mx, v[u]);
                }
                #pragma unroll
                for (int o = 16; o > 0; o >>= 1)
                    mx = fmaxf(mx, __shfl_xor_sync(0xffffffffu, mx, o));
                float ssum = 0.f;
                #pragma unroll
                for (int u = 0; u < C_ / 32; u++) {
                    v[u] = __expf(v[u] - mx);
                    ssum += v[u];
                }
                #pragma unroll
                for (int o = 16; o > 0; o >>= 1)
                    ssum += __shfl_xor_sync(0xffffffffu, ssum, o);
                float inv = 1.0f / ssum;
                #pragma unroll
                for (int u = 0; u < C_ / 32; u++)
                    sPT[(lid + 32 * u) * PT_STRIDE + r] = v[u] * inv;
            }
            __syncthreads();
        }

        // ---- GEMM2: fq_new[t][i] = sum_c Fq[t][c] * P[i][c]; fold into num/norm2 ----
        {
            const int tg = tid & 31;   // t = tg + 32*m
            const int ig = tid >> 5;   // i = ig*4 + j
            float acc2[7][4];
            #pragma unroll
            for (int m = 0; m < 7; m++)
                #pragma unroll
                for (int j = 0; j < 4; j++) acc2[m][j] = 0.f;

            for (int c0 = 0; c0 < C_; c0 += CK) {
                // stage Fq chunk transposed: sFq[cc][t]
                for (int idx = tid; idx < CK * T_; idx += TPB) {
                    int cc = idx & 31;
                    int t  = idx >> 5;
                    sFq[cc * SFQ_STRIDE + t] = Fq[t * C_ + c0 + cc];
                }
                __syncthreads();
                #pragma unroll
                for (int cc = 0; cc < CK; cc++) {
                    float b0 = sPT[(c0 + cc) * PT_STRIDE + ig * 4 + 0];
                    float b1 = sPT[(c0 + cc) * PT_STRIDE + ig * 4 + 1];
                    float b2 = sPT[(c0 + cc) * PT_STRIDE + ig * 4 + 2];
                    float b3 = sPT[(c0 + cc) * PT_STRIDE + ig * 4 + 3];
                    #pragma unroll
                    for (int m = 0; m < 7; m++) {
                        float a = sFq[cc * SFQ_STRIDE + tg + 32 * m];
                        acc2[m][0] += a * b0;
                        acc2[m][1] += a * b1;
                        acc2[m][2] += a * b2;
                        acc2[m][3] += a * b3;
                    }
                }
                __syncthreads();
            }
            // deterministic per-warpgroup partials
            #pragma unroll
            for (int m = 0; m < 7; m++) {
                int t = tg + 32 * m;
                if (t < T_) {
                    float4 fsv = *(const float4*)&Fs[t * C_ + d0 + ig * 4];
                    float pn = acc2[m][0] * fsv.x + acc2[m][1] * fsv.y +
                               acc2[m][2] * fsv.z + acc2[m][3] * fsv.w;
                    float pq = acc2[m][0] * acc2[m][0] + acc2[m][1] * acc2[m][1] +
                               acc2[m][2] * acc2[m][2] + acc2[m][3] * acc2[m][3];
                    sPN[ig * T_ + t] = pn;
                    sPQ[ig * T_ + t] = pq;
                }
            }
            __syncthreads();
            for (int t = tid; t < T_; t += TPB) {
                float an = sNum[t], aq = sNrm[t];
                #pragma unroll
                for (int g = 0; g < 8; g++) {
                    an += sPN[g * T_ + t];
                    aq += sPQ[g * T_ + t];
                }
                sNum[t] = an;
                sNrm[t] = aq;
            }
            __syncthreads();
        }
    }  // d-tile loop

    // ---- cosine sim per token, max over tokens ----
    float local = -INFINITY;
    for (int t = tid; t < T_; t += TPB) {
        float denom = fmaxf(sqrtf(sNrm[t]) * sNfs[t], 1e-8f);
        local = fmaxf(local, sNum[t] / denom);
    }
    #pragma unroll
    for (int o = 16; o > 0; o >>= 1)
        local = fmaxf(local, __shfl_xor_sync(0xffffffffu, local, o));
    if (lid == 0) sRed[wid] = local;
    __syncthreads();
    if (tid == 0) {
        float m = sRed[0];
        #pragma unroll
        for (int w = 1; w < 8; w++) m = fmaxf(m, sRed[w]);
        g_top1[bx] = m;
    }
}

__global__ void finalize_logits_kernel(float* __restrict__ out) {
    int i = blockIdx.x * blockDim.x + threadIdx.x;
    if (i < B_ * Q_) {
        float s = 0.f;
        #pragma unroll
        for (int n = 0; n < N_; n++) s += g_top1[i * N_ + n];
        out[i] = s * (1.0f / N_);
    }
}

__global__ void cls_kernel(const float* __restrict__ xq,
                           const float* __restrict__ xs,
                           float* __restrict__ out) {
    int w = (blockIdx.x * blockDim.x + threadIdx.x) >> 5;
    int lid = threadIdx.x & 31;
    if (w >= B_ * Q_ * N_) return;
    int nn = w % N_;
    int qq = (w / N_) % Q_;
    int bb = w / (N_ * Q_);
    const float* q = xq + (size_t)(bb * Q_ + qq) * D_;
    const float* s = xs + (size_t)(bb * N_ + nn) * D_;
    float dot = 0.f, nq = 0.f, ns = 0.f;
    #pragma unroll
    for (int u = 0; u < D_ / 32; u++) {
        float a = q[lid + 32 * u];
        float b = s[lid + 32 * u];
        dot += a * b;
        nq += a * a;
        ns += b * b;
    }
    #pragma unroll
    for (int o = 16; o > 0; o >>= 1) {
        dot += __shfl_xor_sync(0xffffffffu, dot, o);
        nq  += __shfl_xor_sync(0xffffffffu, nq, o);
        ns  += __shfl_xor_sync(0xffffffffu, ns, o);
    }
    if (lid == 0) {
        float den = fmaxf(sqrtf(nq), 1e-12f) * fmaxf(sqrtf(ns), 1e-12f);
        out[B_ * Q_ + w] = 10.0f * dot / den;
    }
}

extern "C" void kernel_launch(void* const* d_in, const int* in_sizes, int n_in,
                              void* d_out, int out_size) {
    const float* fq = (const float*)d_in[0];  // (2,75,196,384)
    const float* fs = (const float*)d_in[1];  // (2,5,1,196,384)
    const float* xq = (const float*)d_in[2];  // (2,75,384)
    const float* xs = (const float*)d_in[3];  // (2,5,1,384)
    float* out = (float*)d_out;               // [150 logits][750 cls_logits]

    const size_t smem_bytes = (size_t)SMEM_FLOATS * sizeof(float);
    cudaFuncSetAttribute(episodic_main_kernel,
                         cudaFuncAttributeMaxDynamicSharedMemorySize,
                         (int)smem_bytes);

    episodic_main_kernel<<<B_ * Q_ * N_, TPB, smem_bytes>>>(fq, fs);
    finalize_logits_kernel<<<1, 256>>>(out);
    cls_kernel<<<(B_ * Q_ * N_ * 32 + 255) / 256, 256>>>(xq, xs, out);
}